// round 13
// baseline (speedup 1.0000x reference)
#include <cuda_runtime.h>
#include <cuda_bf16.h>
#include <cuda_fp16.h>
#include <cstdint>

// Sliding-window causal attention; QK^T bf16 3-product split, PV fp16 single
// product with FA2 online row-max in log2 domain (Q pre-scaled by log2e,
// exponentials via ex2.approx.f32). V fragments via ldmatrix.trans.
// B*H=64, S=4096, D=64, WINDOW=256; mask j in [max(i-255,0), i]; no 1/sqrt(d).

#define S_LEN   4096
#define DIM     64
#define WINDOW  256
#define MQ_CTA  128       // queries per CTA
#define NTHREADS 256      // 8 warps, 16 rows each
#define TKEYS   128       // keys per streamed tile
#define NTILES  3         // tiles covering [q0-256, q0+128)
#define KSTRIDE 72        // elems per row: 144B, 16 mod 128 -> conflict-free ldmatrix
#define KROWB   144

// per-tile buffer: K hi (bf16), K lo (bf16), V (fp16), each 128 x 72 elems = 18432B
#define T_KHI 0
#define T_KLO 18432
#define T_V   36864
#define TILE_BYTES 55296
#define SMEM_TOTAL (2 * TILE_BYTES)   // 110592 B -> 2 CTAs/SM

#define LOG2E 1.4426950408889634f

__device__ __forceinline__ void mma_bf16(float* c, const uint32_t* a, const uint32_t* b) {
    asm volatile(
        "mma.sync.aligned.m16n8k16.row.col.f32.bf16.bf16.f32 "
        "{%0,%1,%2,%3}, {%4,%5,%6,%7}, {%8,%9}, {%0,%1,%2,%3};"
        : "+f"(c[0]), "+f"(c[1]), "+f"(c[2]), "+f"(c[3])
        : "r"(a[0]), "r"(a[1]), "r"(a[2]), "r"(a[3]), "r"(b[0]), "r"(b[1]));
}
__device__ __forceinline__ void mma_fp16(float* c, const uint32_t* a, const uint32_t* b) {
    asm volatile(
        "mma.sync.aligned.m16n8k16.row.col.f32.f16.f16.f32 "
        "{%0,%1,%2,%3}, {%4,%5,%6,%7}, {%8,%9}, {%0,%1,%2,%3};"
        : "+f"(c[0]), "+f"(c[1]), "+f"(c[2]), "+f"(c[3])
        : "r"(a[0]), "r"(a[1]), "r"(a[2]), "r"(a[3]), "r"(b[0]), "r"(b[1]));
}

#define LDMX4(r0, r1, r2, r3, a) \
    asm volatile("ldmatrix.sync.aligned.m8n8.x4.shared.b16 {%0,%1,%2,%3}, [%4];" \
        : "=r"(r0), "=r"(r1), "=r"(r2), "=r"(r3) : "r"(a))
#define LDMX4T(r0, r1, r2, r3, a) \
    asm volatile("ldmatrix.sync.aligned.m8n8.x4.trans.shared.b16 {%0,%1,%2,%3}, [%4];" \
        : "=r"(r0), "=r"(r1), "=r"(r2), "=r"(r3) : "r"(a))

__device__ __forceinline__ float ex2f(float x) {
    float y;
    asm("ex2.approx.f32 %0, %1;" : "=f"(y) : "f"(x));
    return y;
}
__device__ __forceinline__ void split2(float a, float b, uint32_t& hi, uint32_t& lo) {
    __nv_bfloat16 h0 = __float2bfloat16(a);
    __nv_bfloat16 h1 = __float2bfloat16(b);
    __nv_bfloat16 g0 = __float2bfloat16(a - __bfloat162float(h0));
    __nv_bfloat16 g1 = __float2bfloat16(b - __bfloat162float(h1));
    __nv_bfloat162 H; H.x = h0; H.y = h1;
    __nv_bfloat162 G; G.x = g0; G.y = g1;
    hi = *reinterpret_cast<uint32_t*>(&H);
    lo = *reinterpret_cast<uint32_t*>(&G);
}
__device__ __forceinline__ uint32_t packh2(float a, float b) {
    __half2 h = __floats2half2_rn(a, b);
    return *reinterpret_cast<uint32_t*>(&h);
}

__global__ __launch_bounds__(NTHREADS, 2)
void swa_mma_kernel(const float* __restrict__ qg,
                    const float* __restrict__ kg,
                    const float* __restrict__ vg,
                    float* __restrict__ og)
{
    extern __shared__ char sm[];
    const uint32_t smem_b = (uint32_t)__cvta_generic_to_shared(sm);

    const int tid  = threadIdx.x;
    const int lane = tid & 31;
    const int warp = tid >> 5;
    const int g    = lane >> 2;
    const int tg   = lane & 3;
    const int q0   = blockIdx.x * MQ_CTA;
    const long long base = (long long)blockIdx.y * (S_LEN * DIM);

    const uint32_t k_lane = (uint32_t)(((lane & 7) + 8 * ((lane >> 3) & 1)) * KROWB
                                       + (lane >> 4) * 16);               // non-trans (K)
    const uint32_t v_lane = (uint32_t)((lane & 15) * KROWB + ((lane >> 4) << 4)); // trans (V)

    // ---- stage Q via smem (32 KB, overlays tile buffers), build A-fragments.
    //      Q is pre-scaled by log2e so scores come out in log2 units. ----
    {
        float* qstage = (float*)sm;
        const float4* qp = (const float4*)(qg + base + (long long)q0 * DIM);
        float4* st = (float4*)qstage;
        #pragma unroll
        for (int e = tid; e < MQ_CTA * 16; e += NTHREADS) st[e] = qp[e];
        __syncthreads();
    }
    uint32_t qfh[4][4], qfl[4][4];
    {
        const float* qstage = (const float*)sm;
        const int rr = 16 * warp + g;
        #pragma unroll
        for (int s = 0; s < 4; s++) {
            const int c = 16 * s + tg * 2;
            float2 x0 = *(const float2*)(qstage + rr * DIM + c);
            float2 x1 = *(const float2*)(qstage + (rr + 8) * DIM + c);
            float2 x2 = *(const float2*)(qstage + rr * DIM + c + 8);
            float2 x3 = *(const float2*)(qstage + (rr + 8) * DIM + c + 8);
            split2(x0.x * LOG2E, x0.y * LOG2E, qfh[s][0], qfl[s][0]);
            split2(x1.x * LOG2E, x1.y * LOG2E, qfh[s][1], qfl[s][1]);
            split2(x2.x * LOG2E, x2.y * LOG2E, qfh[s][2], qfl[s][2]);
            split2(x3.x * LOG2E, x3.y * LOG2E, qfh[s][3], qfl[s][3]);
        }
    }
    __syncthreads();

    // ---- tile loader: 128 keys -> K hi/lo (bf16) + V (fp16), key-major ----
    auto load_tile = [&](int t, int buf) {
        char* tb = sm + buf * TILE_BYTES;
        const int kt_a = q0 - WINDOW + t * TKEYS;
        #pragma unroll
        for (int e = tid; e < TKEYS * 16; e += NTHREADS) {   // 8 iterations
            const int jj = e >> 4, c4 = e & 15;
            const int ja = kt_a + jj;
            float4 kk = make_float4(0.f, 0.f, 0.f, 0.f), vv = kk;
            if (ja >= 0) {
                const long long off = base + (long long)ja * DIM;
                kk = ((const float4*)(kg + off))[c4];
                vv = ((const float4*)(vg + off))[c4];
            }
            const uint32_t ro = (uint32_t)(jj * KROWB + c4 * 8);
            uint2 h, l;
            split2(kk.x, kk.y, h.x, l.x);
            split2(kk.z, kk.w, h.y, l.y);
            *(uint2*)(tb + T_KHI + ro) = h;
            *(uint2*)(tb + T_KLO + ro) = l;
            uint2 vp;
            vp.x = packh2(vv.x, vv.y);
            vp.y = packh2(vv.z, vv.w);
            *(uint2*)(tb + T_V + ro) = vp;
        }
    };

    float oacc[8][4];
    #pragma unroll
    for (int n = 0; n < 8; n++)
        #pragma unroll
        for (int c = 0; c < 4; c++) oacc[n][c] = 0.f;
    float lsum0 = 0.f, lsum1 = 0.f;
    float m0 = -1e30f, m1 = -1e30f;   // running max in log2 units

    const int rw = q0 + 16 * warp;
    const int r0 = rw + g;
    const int r1 = r0 + 8;

    load_tile(0, 0);
    __syncthreads();

    for (int t = 0; t < NTILES; t++) {
        if (t + 1 < NTILES) load_tile(t + 1, (t + 1) & 1);

        const uint32_t tbu = smem_b + (uint32_t)((t & 1) * TILE_BYTES);
        const int kt_a = q0 - WINDOW + t * TKEYS;

        #pragma unroll
        for (int sblk = 0; sblk < 4; sblk++) {
            const int ktr = 32 * sblk;
            const int kta = kt_a + ktr;
            if (kta + 31 < rw - (WINDOW - 1) || kta > rw + 15 || kta + 31 < 0) continue;

            const bool fast = (kta >= 0) && (kta >= rw - (WINDOW - 16)) && (kta + 31 <= rw);

            // ---- S (log2 units) = (Q*log2e) K^T, bf16 3-product ----
            float sacc[4][4];
            #pragma unroll
            for (int n = 0; n < 4; n++)
                #pragma unroll
                for (int c = 0; c < 4; c++) sacc[n][c] = 0.f;

            const uint32_t kb = tbu + T_KHI + (uint32_t)(ktr * KROWB) + k_lane;
            #pragma unroll
            for (int ks = 0; ks < 4; ks++) {
                uint32_t bh[4][2], bl[4][2];
                #pragma unroll
                for (int p = 0; p < 2; p++) {
                    const uint32_t ah = kb + (uint32_t)(p * 16 * KROWB + ks * 32);
                    LDMX4(bh[2*p][0], bh[2*p+1][0], bh[2*p][1], bh[2*p+1][1], ah);
                    LDMX4(bl[2*p][0], bl[2*p+1][0], bl[2*p][1], bl[2*p+1][1],
                          ah + (T_KLO - T_KHI));
                }
                #pragma unroll
                for (int nt = 0; nt < 4; nt++) {
                    mma_bf16(sacc[nt], qfh[ks], bh[nt]);
                    mma_bf16(sacc[nt], qfh[ks], bl[nt]);
                    mma_bf16(sacc[nt], qfl[ks], bh[nt]);
                }
            }

            // ---- mask (slow path), online max, conditional rescale ----
            if (!fast) {
                #pragma unroll
                for (int nt = 0; nt < 4; nt++) {
                    const int j0 = kta + 8 * nt + tg * 2;
                    const int j1 = j0 + 1;
                    if (!((unsigned)(r0 - j0) < 256u && j0 >= 0)) sacc[nt][0] = -1e30f;
                    if (!((unsigned)(r0 - j1) < 256u && j1 >= 0)) sacc[nt][1] = -1e30f;
                    if (!((unsigned)(r1 - j0) < 256u && j0 >= 0)) sacc[nt][2] = -1e30f;
                    if (!((unsigned)(r1 - j1) < 256u && j1 >= 0)) sacc[nt][3] = -1e30f;
                }
            }
            float mx0 = fmaxf(fmaxf(fmaxf(sacc[0][0], sacc[0][1]), fmaxf(sacc[1][0], sacc[1][1])),
                              fmaxf(fmaxf(sacc[2][0], sacc[2][1]), fmaxf(sacc[3][0], sacc[3][1])));
            float mx1 = fmaxf(fmaxf(fmaxf(sacc[0][2], sacc[0][3]), fmaxf(sacc[1][2], sacc[1][3])),
                              fmaxf(fmaxf(sacc[2][2], sacc[2][3]), fmaxf(sacc[3][2], sacc[3][3])));
            mx0 = fmaxf(mx0, __shfl_xor_sync(0xffffffffu, mx0, 1));
            mx0 = fmaxf(mx0, __shfl_xor_sync(0xffffffffu, mx0, 2));
            mx1 = fmaxf(mx1, __shfl_xor_sync(0xffffffffu, mx1, 1));
            mx1 = fmaxf(mx1, __shfl_xor_sync(0xffffffffu, mx1, 2));
            const float m0n = fmaxf(m0, mx0);
            const float m1n = fmaxf(m1, mx1);
            const bool nochange = (m0n == m0) && (m1n == m1);
            if (!__all_sync(0xffffffffu, nochange)) {
                const float a0 = ex2f(m0 - m0n);
                const float a1 = ex2f(m1 - m1n);
                lsum0 *= a0; lsum1 *= a1;
                #pragma unroll
                for (int nt = 0; nt < 8; nt++) {
                    oacc[nt][0] *= a0; oacc[nt][1] *= a0;
                    oacc[nt][2] *= a1; oacc[nt][3] *= a1;
                }
                m0 = m0n; m1 = m1n;
            }

            // ---- p = 2^(s - m), pack P (fp16) ----
            uint32_t pf[2][4];
            if (fast) {
                #pragma unroll
                for (int nt = 0; nt < 4; nt++) {
                    const float p0 = ex2f(sacc[nt][0] - m0);
                    const float p1 = ex2f(sacc[nt][1] - m0);
                    const float p2 = ex2f(sacc[nt][2] - m1);
                    const float p3 = ex2f(sacc[nt][3] - m1);
                    lsum0 += p0 + p1;
                    lsum1 += p2 + p3;
                    const int kk = nt >> 1;
                    const int hh = (nt & 1) ? 2 : 0;
                    pf[kk][hh + 0] = packh2(p0, p1);
                    pf[kk][hh + 1] = packh2(p2, p3);
                }
            } else {
                #pragma unroll
                for (int nt = 0; nt < 4; nt++) {
                    const float p0 = (sacc[nt][0] > -1e29f) ? ex2f(sacc[nt][0] - m0) : 0.f;
                    const float p1 = (sacc[nt][1] > -1e29f) ? ex2f(sacc[nt][1] - m0) : 0.f;
                    const float p2 = (sacc[nt][2] > -1e29f) ? ex2f(sacc[nt][2] - m1) : 0.f;
                    const float p3 = (sacc[nt][3] > -1e29f) ? ex2f(sacc[nt][3] - m1) : 0.f;
                    lsum0 += p0 + p1;
                    lsum1 += p2 + p3;
                    const int kk = nt >> 1;
                    const int hh = (nt & 1) ? 2 : 0;
                    pf[kk][hh + 0] = packh2(p0, p1);
                    pf[kk][hh + 1] = packh2(p2, p3);
                }
            }

            // ---- O += P V (fp16), V-frags via ldmatrix.trans ----
            #pragma unroll
            for (int kk = 0; kk < 2; kk++) {
                const uint32_t vb = tbu + T_V + (uint32_t)((ktr + 16 * kk) * KROWB) + v_lane;
                #pragma unroll
                for (int p = 0; p < 4; p++) {
                    uint32_t vt[4];
                    LDMX4T(vt[0], vt[1], vt[2], vt[3], vb + (uint32_t)(p * 32));
                    mma_fp16(oacc[2*p],     pf[kk], vt);
                    mma_fp16(oacc[2*p + 1], pf[kk], vt + 2);
                }
            }
        }
        __syncthreads();
    }

    // ---- epilogue: quad-reduce row sums, normalize, store ----
    lsum0 += __shfl_xor_sync(0xffffffffu, lsum0, 1);
    lsum0 += __shfl_xor_sync(0xffffffffu, lsum0, 2);
    lsum1 += __shfl_xor_sync(0xffffffffu, lsum1, 1);
    lsum1 += __shfl_xor_sync(0xffffffffu, lsum1, 2);
    const float inv0 = 1.0f / lsum0;
    const float inv1 = 1.0f / lsum1;

    float* o0 = og + base + (long long)r0 * DIM;
    float* o1 = og + base + (long long)r1 * DIM;
    #pragma unroll
    for (int nt = 0; nt < 8; nt++) {
        const int d = 8 * nt + tg * 2;
        *(float2*)(o0 + d) = make_float2(oacc[nt][0] * inv0, oacc[nt][1] * inv0);
        *(float2*)(o1 + d) = make_float2(oacc[nt][2] * inv1, oacc[nt][3] * inv1);
    }
}

extern "C" void kernel_launch(void* const* d_in, const int* in_sizes, int n_in,
                              void* d_out, int out_size)
{
    const float* q = (const float*)d_in[0];
    const float* k = (const float*)d_in[1];
    const float* v = (const float*)d_in[2];
    float* out = (float*)d_out;

    static bool configured = false;
    if (!configured) {
        cudaFuncSetAttribute(swa_mma_kernel,
                             cudaFuncAttributeMaxDynamicSharedMemorySize, SMEM_TOTAL);
        configured = true;
    }

    const int BH = in_sizes[0] / (S_LEN * DIM);
    dim3 grid(S_LEN / MQ_CTA, BH);
    swa_mma_kernel<<<grid, NTHREADS, SMEM_TOTAL>>>(q, k, v, out);
}

// round 14
// speedup vs baseline: 1.0082x; 1.0082x over previous
#include <cuda_runtime.h>
#include <cuda_bf16.h>
#include <cuda_fp16.h>
#include <cstdint>

// Sliding-window causal attention; QK^T bf16 3-product split, PV fp16 single
// product with FA2 online row-max in log2 domain (Q pre-scaled by log2e,
// exponentials via ex2.approx.f32). V fragments via ldmatrix.trans.
// B*H=64, S=4096, D=64, WINDOW=256; mask j in [max(i-255,0), i]; no 1/sqrt(d).

#define S_LEN   4096
#define DIM     64
#define WINDOW  256
#define MQ_CTA  128       // queries per CTA
#define NTHREADS 256      // 8 warps, 16 rows each
#define TKEYS   128       // keys per streamed tile
#define NTILES  3         // tiles covering [q0-256, q0+128)
#define KSTRIDE 72        // elems per row: 144B, 16 mod 128 -> conflict-free ldmatrix
#define KROWB   144

// per-tile buffer: K hi (bf16), K lo (bf16), V (fp16), each 128 x 72 elems = 18432B
#define T_KHI 0
#define T_KLO 18432
#define T_V   36864
#define TILE_BYTES 55296
#define SMEM_TOTAL (2 * TILE_BYTES)   // 110592 B -> 2 CTAs/SM

#define LOG2E 1.4426950408889634f

__device__ __forceinline__ void mma_bf16(float* c, const uint32_t* a, const uint32_t* b) {
    asm volatile(
        "mma.sync.aligned.m16n8k16.row.col.f32.bf16.bf16.f32 "
        "{%0,%1,%2,%3}, {%4,%5,%6,%7}, {%8,%9}, {%0,%1,%2,%3};"
        : "+f"(c[0]), "+f"(c[1]), "+f"(c[2]), "+f"(c[3])
        : "r"(a[0]), "r"(a[1]), "r"(a[2]), "r"(a[3]), "r"(b[0]), "r"(b[1]));
}
__device__ __forceinline__ void mma_fp16(float* c, const uint32_t* a, const uint32_t* b) {
    asm volatile(
        "mma.sync.aligned.m16n8k16.row.col.f32.f16.f16.f32 "
        "{%0,%1,%2,%3}, {%4,%5,%6,%7}, {%8,%9}, {%0,%1,%2,%3};"
        : "+f"(c[0]), "+f"(c[1]), "+f"(c[2]), "+f"(c[3])
        : "r"(a[0]), "r"(a[1]), "r"(a[2]), "r"(a[3]), "r"(b[0]), "r"(b[1]));
}

#define LDMX4(r0, r1, r2, r3, a) \
    asm volatile("ldmatrix.sync.aligned.m8n8.x4.shared.b16 {%0,%1,%2,%3}, [%4];" \
        : "=r"(r0), "=r"(r1), "=r"(r2), "=r"(r3) : "r"(a))
#define LDMX4T(r0, r1, r2, r3, a) \
    asm volatile("ldmatrix.sync.aligned.m8n8.x4.trans.shared.b16 {%0,%1,%2,%3}, [%4];" \
        : "=r"(r0), "=r"(r1), "=r"(r2), "=r"(r3) : "r"(a))

__device__ __forceinline__ float ex2f(float x) {
    float y;
    asm("ex2.approx.f32 %0, %1;" : "=f"(y) : "f"(x));
    return y;
}
__device__ __forceinline__ void split2(float a, float b, uint32_t& hi, uint32_t& lo) {
    __nv_bfloat16 h0 = __float2bfloat16(a);
    __nv_bfloat16 h1 = __float2bfloat16(b);
    __nv_bfloat16 g0 = __float2bfloat16(a - __bfloat162float(h0));
    __nv_bfloat16 g1 = __float2bfloat16(b - __bfloat162float(h1));
    __nv_bfloat162 H; H.x = h0; H.y = h1;
    __nv_bfloat162 G; G.x = g0; G.y = g1;
    hi = *reinterpret_cast<uint32_t*>(&H);
    lo = *reinterpret_cast<uint32_t*>(&G);
}
__device__ __forceinline__ uint32_t packh2(float a, float b) {
    __half2 h = __floats2half2_rn(a, b);
    return *reinterpret_cast<uint32_t*>(&h);
}

__global__ __launch_bounds__(NTHREADS, 2)
void swa_mma_kernel(const float* __restrict__ qg,
                    const float* __restrict__ kg,
                    const float* __restrict__ vg,
                    float* __restrict__ og)
{
    extern __shared__ char sm[];
    const uint32_t smem_b = (uint32_t)__cvta_generic_to_shared(sm);

    const int tid  = threadIdx.x;
    const int lane = tid & 31;
    const int warp = tid >> 5;
    const int g    = lane >> 2;
    const int tg   = lane & 3;
    const int q0   = blockIdx.x * MQ_CTA;
    const long long base = (long long)blockIdx.y * (S_LEN * DIM);

    const uint32_t k_lane = (uint32_t)(((lane & 7) + 8 * ((lane >> 3) & 1)) * KROWB
                                       + (lane >> 4) * 16);               // non-trans (K)
    const uint32_t v_lane = (uint32_t)((lane & 15) * KROWB + ((lane >> 4) << 4)); // trans (V)

    // ---- stage Q via smem (32 KB, overlays tile buffers), build A-fragments.
    //      Q is pre-scaled by log2e so scores come out in log2 units. ----
    {
        float* qstage = (float*)sm;
        const float4* qp = (const float4*)(qg + base + (long long)q0 * DIM);
        float4* st = (float4*)qstage;
        #pragma unroll
        for (int e = tid; e < MQ_CTA * 16; e += NTHREADS) st[e] = qp[e];
        __syncthreads();
    }
    uint32_t qfh[4][4], qfl[4][4];
    {
        const float* qstage = (const float*)sm;
        const int rr = 16 * warp + g;
        #pragma unroll
        for (int s = 0; s < 4; s++) {
            const int c = 16 * s + tg * 2;
            float2 x0 = *(const float2*)(qstage + rr * DIM + c);
            float2 x1 = *(const float2*)(qstage + (rr + 8) * DIM + c);
            float2 x2 = *(const float2*)(qstage + rr * DIM + c + 8);
            float2 x3 = *(const float2*)(qstage + (rr + 8) * DIM + c + 8);
            split2(x0.x * LOG2E, x0.y * LOG2E, qfh[s][0], qfl[s][0]);
            split2(x1.x * LOG2E, x1.y * LOG2E, qfh[s][1], qfl[s][1]);
            split2(x2.x * LOG2E, x2.y * LOG2E, qfh[s][2], qfl[s][2]);
            split2(x3.x * LOG2E, x3.y * LOG2E, qfh[s][3], qfl[s][3]);
        }
    }
    __syncthreads();

    // ---- tile loader: 128 keys -> K hi/lo (bf16) + V (fp16), key-major ----
    auto load_tile = [&](int t, int buf) {
        char* tb = sm + buf * TILE_BYTES;
        const int kt_a = q0 - WINDOW + t * TKEYS;
        #pragma unroll
        for (int e = tid; e < TKEYS * 16; e += NTHREADS) {   // 8 iterations
            const int jj = e >> 4, c4 = e & 15;
            const int ja = kt_a + jj;
            float4 kk = make_float4(0.f, 0.f, 0.f, 0.f), vv = kk;
            if (ja >= 0) {
                const long long off = base + (long long)ja * DIM;
                kk = ((const float4*)(kg + off))[c4];
                vv = ((const float4*)(vg + off))[c4];
            }
            const uint32_t ro = (uint32_t)(jj * KROWB + c4 * 8);
            uint2 h, l;
            split2(kk.x, kk.y, h.x, l.x);
            split2(kk.z, kk.w, h.y, l.y);
            *(uint2*)(tb + T_KHI + ro) = h;
            *(uint2*)(tb + T_KLO + ro) = l;
            uint2 vp;
            vp.x = packh2(vv.x, vv.y);
            vp.y = packh2(vv.z, vv.w);
            *(uint2*)(tb + T_V + ro) = vp;
        }
    };

    float oacc[8][4];
    #pragma unroll
    for (int n = 0; n < 8; n++)
        #pragma unroll
        for (int c = 0; c < 4; c++) oacc[n][c] = 0.f;
    float lsum0 = 0.f, lsum1 = 0.f;
    float m0 = -1e30f, m1 = -1e30f;   // running max in log2 units

    const int rw = q0 + 16 * warp;
    const int r0 = rw + g;
    const int r1 = r0 + 8;

    load_tile(0, 0);
    __syncthreads();

    for (int t = 0; t < NTILES; t++) {
        if (t + 1 < NTILES) load_tile(t + 1, (t + 1) & 1);

        const uint32_t tbu = smem_b + (uint32_t)((t & 1) * TILE_BYTES);
        const int kt_a = q0 - WINDOW + t * TKEYS;

        #pragma unroll
        for (int sblk = 0; sblk < 4; sblk++) {
            const int ktr = 32 * sblk;
            const int kta = kt_a + ktr;
            if (kta + 31 < rw - (WINDOW - 1) || kta > rw + 15 || kta + 31 < 0) continue;

            const bool fast = (kta >= 0) && (kta >= rw - (WINDOW - 16)) && (kta + 31 <= rw);

            // ---- S (log2 units) = (Q*log2e) K^T, bf16 3-product ----
            float sacc[4][4];
            #pragma unroll
            for (int n = 0; n < 4; n++)
                #pragma unroll
                for (int c = 0; c < 4; c++) sacc[n][c] = 0.f;

            const uint32_t kb = tbu + T_KHI + (uint32_t)(ktr * KROWB) + k_lane;
            #pragma unroll
            for (int ks = 0; ks < 4; ks++) {
                uint32_t bh[4][2], bl[4][2];
                #pragma unroll
                for (int p = 0; p < 2; p++) {
                    const uint32_t ah = kb + (uint32_t)(p * 16 * KROWB + ks * 32);
                    LDMX4(bh[2*p][0], bh[2*p+1][0], bh[2*p][1], bh[2*p+1][1], ah);
                    LDMX4(bl[2*p][0], bl[2*p+1][0], bl[2*p][1], bl[2*p+1][1],
                          ah + (T_KLO - T_KHI));
                }
                #pragma unroll
                for (int nt = 0; nt < 4; nt++) {
                    mma_bf16(sacc[nt], qfh[ks], bh[nt]);
                    mma_bf16(sacc[nt], qfh[ks], bl[nt]);
                    mma_bf16(sacc[nt], qfl[ks], bh[nt]);
                }
            }

            // ---- mask (slow path), online max, conditional rescale ----
            if (!fast) {
                #pragma unroll
                for (int nt = 0; nt < 4; nt++) {
                    const int j0 = kta + 8 * nt + tg * 2;
                    const int j1 = j0 + 1;
                    if (!((unsigned)(r0 - j0) < 256u && j0 >= 0)) sacc[nt][0] = -1e30f;
                    if (!((unsigned)(r0 - j1) < 256u && j1 >= 0)) sacc[nt][1] = -1e30f;
                    if (!((unsigned)(r1 - j0) < 256u && j0 >= 0)) sacc[nt][2] = -1e30f;
                    if (!((unsigned)(r1 - j1) < 256u && j1 >= 0)) sacc[nt][3] = -1e30f;
                }
            }
            float mx0 = fmaxf(fmaxf(fmaxf(sacc[0][0], sacc[0][1]), fmaxf(sacc[1][0], sacc[1][1])),
                              fmaxf(fmaxf(sacc[2][0], sacc[2][1]), fmaxf(sacc[3][0], sacc[3][1])));
            float mx1 = fmaxf(fmaxf(fmaxf(sacc[0][2], sacc[0][3]), fmaxf(sacc[1][2], sacc[1][3])),
                              fmaxf(fmaxf(sacc[2][2], sacc[2][3]), fmaxf(sacc[3][2], sacc[3][3])));
            mx0 = fmaxf(mx0, __shfl_xor_sync(0xffffffffu, mx0, 1));
            mx0 = fmaxf(mx0, __shfl_xor_sync(0xffffffffu, mx0, 2));
            mx1 = fmaxf(mx1, __shfl_xor_sync(0xffffffffu, mx1, 1));
            mx1 = fmaxf(mx1, __shfl_xor_sync(0xffffffffu, mx1, 2));
            const float m0n = fmaxf(m0, mx0);
            const float m1n = fmaxf(m1, mx1);
            const bool nochange = (m0n == m0) && (m1n == m1);
            if (!__all_sync(0xffffffffu, nochange)) {
                const float a0 = ex2f(m0 - m0n);
                const float a1 = ex2f(m1 - m1n);
                lsum0 *= a0; lsum1 *= a1;
                #pragma unroll
                for (int nt = 0; nt < 8; nt++) {
                    oacc[nt][0] *= a0; oacc[nt][1] *= a0;
                    oacc[nt][2] *= a1; oacc[nt][3] *= a1;
                }
                m0 = m0n; m1 = m1n;
            }

            // ---- p = 2^(s - m), pack P (fp16) ----
            uint32_t pf[2][4];
            if (fast) {
                #pragma unroll
                for (int nt = 0; nt < 4; nt++) {
                    const float p0 = ex2f(sacc[nt][0] - m0);
                    const float p1 = ex2f(sacc[nt][1] - m0);
                    const float p2 = ex2f(sacc[nt][2] - m1);
                    const float p3 = ex2f(sacc[nt][3] - m1);
                    lsum0 += p0 + p1;
                    lsum1 += p2 + p3;
                    const int kk = nt >> 1;
                    const int hh = (nt & 1) ? 2 : 0;
                    pf[kk][hh + 0] = packh2(p0, p1);
                    pf[kk][hh + 1] = packh2(p2, p3);
                }
            } else {
                #pragma unroll
                for (int nt = 0; nt < 4; nt++) {
                    const float p0 = (sacc[nt][0] > -1e29f) ? ex2f(sacc[nt][0] - m0) : 0.f;
                    const float p1 = (sacc[nt][1] > -1e29f) ? ex2f(sacc[nt][1] - m0) : 0.f;
                    const float p2 = (sacc[nt][2] > -1e29f) ? ex2f(sacc[nt][2] - m1) : 0.f;
                    const float p3 = (sacc[nt][3] > -1e29f) ? ex2f(sacc[nt][3] - m1) : 0.f;
                    lsum0 += p0 + p1;
                    lsum1 += p2 + p3;
                    const int kk = nt >> 1;
                    const int hh = (nt & 1) ? 2 : 0;
                    pf[kk][hh + 0] = packh2(p0, p1);
                    pf[kk][hh + 1] = packh2(p2, p3);
                }
            }

            // ---- O += P V (fp16), V-frags via ldmatrix.trans ----
            #pragma unroll
            for (int kk = 0; kk < 2; kk++) {
                const uint32_t vb = tbu + T_V + (uint32_t)((ktr + 16 * kk) * KROWB) + v_lane;
                #pragma unroll
                for (int p = 0; p < 4; p++) {
                    uint32_t vt[4];
                    LDMX4T(vt[0], vt[1], vt[2], vt[3], vb + (uint32_t)(p * 32));
                    mma_fp16(oacc[2*p],     pf[kk], vt);
                    mma_fp16(oacc[2*p + 1], pf[kk], vt + 2);
                }
            }
        }
        __syncthreads();
    }

    // ---- epilogue: quad-reduce row sums, normalize, store ----
    lsum0 += __shfl_xor_sync(0xffffffffu, lsum0, 1);
    lsum0 += __shfl_xor_sync(0xffffffffu, lsum0, 2);
    lsum1 += __shfl_xor_sync(0xffffffffu, lsum1, 1);
    lsum1 += __shfl_xor_sync(0xffffffffu, lsum1, 2);
    const float inv0 = 1.0f / lsum0;
    const float inv1 = 1.0f / lsum1;

    float* o0 = og + base + (long long)r0 * DIM;
    float* o1 = og + base + (long long)r1 * DIM;
    #pragma unroll
    for (int nt = 0; nt < 8; nt++) {
        const int d = 8 * nt + tg * 2;
        *(float2*)(o0 + d) = make_float2(oacc[nt][0] * inv0, oacc[nt][1] * inv0);
        *(float2*)(o1 + d) = make_float2(oacc[nt][2] * inv1, oacc[nt][3] * inv1);
    }
}

extern "C" void kernel_launch(void* const* d_in, const int* in_sizes, int n_in,
                              void* d_out, int out_size)
{
    const float* q = (const float*)d_in[0];
    const float* k = (const float*)d_in[1];
    const float* v = (const float*)d_in[2];
    float* out = (float*)d_out;

    static bool configured = false;
    if (!configured) {
        cudaFuncSetAttribute(swa_mma_kernel,
                             cudaFuncAttributeMaxDynamicSharedMemorySize, SMEM_TOTAL);
        configured = true;
    }

    const int BH = in_sizes[0] / (S_LEN * DIM);
    dim3 grid(S_LEN / MQ_CTA, BH);
    swa_mma_kernel<<<grid, NTHREADS, SMEM_TOTAL>>>(q, k, v, out);
}

// round 15
// speedup vs baseline: 1.0978x; 1.0889x over previous
#include <cuda_runtime.h>
#include <cuda_bf16.h>
#include <cuda_fp16.h>
#include <cstdint>

// Sliding-window causal attention; QK^T bf16 3-product split, PV fp16 single
// product with FA2 online row-max in log2 domain (Q pre-scaled by log2e,
// exponentials via ex2.approx.f32). V fragments via ldmatrix.trans.
// Geometry = R11 best (TKEYS=64, NTILES=6, MQ_CTA=128, 2 CTAs/SM).
// B*H=64, S=4096, D=64, WINDOW=256; mask j in [max(i-255,0), i]; no 1/sqrt(d).

#define S_LEN   4096
#define DIM     64
#define WINDOW  256
#define MQ_CTA  128       // queries per CTA
#define NTHREADS 256      // 8 warps, 16 rows each
#define TKEYS   64        // keys per streamed tile
#define NTILES  6         // tiles covering [q0-256, q0+128)
#define KSTRIDE 72        // elems per row: 144B, 16 mod 128 -> conflict-free ldmatrix
#define KROWB   144

// per-tile buffer: K hi (bf16), K lo (bf16), V (fp16), each 64 x 72 elems = 9216B
#define T_KHI 0
#define T_KLO 9216
#define T_V   18432
#define TILE_BYTES 27648
#define SMEM_TOTAL (2 * TILE_BYTES)   // 55296 B -> 2 CTAs/SM (reg-bound)

#define LOG2E 1.4426950408889634f

__device__ __forceinline__ void mma_bf16(float* c, const uint32_t* a, const uint32_t* b) {
    asm volatile(
        "mma.sync.aligned.m16n8k16.row.col.f32.bf16.bf16.f32 "
        "{%0,%1,%2,%3}, {%4,%5,%6,%7}, {%8,%9}, {%0,%1,%2,%3};"
        : "+f"(c[0]), "+f"(c[1]), "+f"(c[2]), "+f"(c[3])
        : "r"(a[0]), "r"(a[1]), "r"(a[2]), "r"(a[3]), "r"(b[0]), "r"(b[1]));
}
__device__ __forceinline__ void mma_fp16(float* c, const uint32_t* a, const uint32_t* b) {
    asm volatile(
        "mma.sync.aligned.m16n8k16.row.col.f32.f16.f16.f32 "
        "{%0,%1,%2,%3}, {%4,%5,%6,%7}, {%8,%9}, {%0,%1,%2,%3};"
        : "+f"(c[0]), "+f"(c[1]), "+f"(c[2]), "+f"(c[3])
        : "r"(a[0]), "r"(a[1]), "r"(a[2]), "r"(a[3]), "r"(b[0]), "r"(b[1]));
}

#define LDMX4(r0, r1, r2, r3, a) \
    asm volatile("ldmatrix.sync.aligned.m8n8.x4.shared.b16 {%0,%1,%2,%3}, [%4];" \
        : "=r"(r0), "=r"(r1), "=r"(r2), "=r"(r3) : "r"(a))
#define LDMX4T(r0, r1, r2, r3, a) \
    asm volatile("ldmatrix.sync.aligned.m8n8.x4.trans.shared.b16 {%0,%1,%2,%3}, [%4];" \
        : "=r"(r0), "=r"(r1), "=r"(r2), "=r"(r3) : "r"(a))

__device__ __forceinline__ float ex2f(float x) {
    float y;
    asm("ex2.approx.f32 %0, %1;" : "=f"(y) : "f"(x));
    return y;
}
__device__ __forceinline__ void split2(float a, float b, uint32_t& hi, uint32_t& lo) {
    __nv_bfloat16 h0 = __float2bfloat16(a);
    __nv_bfloat16 h1 = __float2bfloat16(b);
    __nv_bfloat16 g0 = __float2bfloat16(a - __bfloat162float(h0));
    __nv_bfloat16 g1 = __float2bfloat16(b - __bfloat162float(h1));
    __nv_bfloat162 H; H.x = h0; H.y = h1;
    __nv_bfloat162 G; G.x = g0; G.y = g1;
    hi = *reinterpret_cast<uint32_t*>(&H);
    lo = *reinterpret_cast<uint32_t*>(&G);
}
__device__ __forceinline__ uint32_t packh2(float a, float b) {
    __half2 h = __floats2half2_rn(a, b);
    return *reinterpret_cast<uint32_t*>(&h);
}

__global__ __launch_bounds__(NTHREADS, 2)
void swa_mma_kernel(const float* __restrict__ qg,
                    const float* __restrict__ kg,
                    const float* __restrict__ vg,
                    float* __restrict__ og)
{
    extern __shared__ char sm[];
    const uint32_t smem_b = (uint32_t)__cvta_generic_to_shared(sm);

    const int tid  = threadIdx.x;
    const int lane = tid & 31;
    const int warp = tid >> 5;
    const int g    = lane >> 2;
    const int tg   = lane & 3;
    const int q0   = blockIdx.x * MQ_CTA;
    const long long base = (long long)blockIdx.y * (S_LEN * DIM);

    const uint32_t k_lane = (uint32_t)(((lane & 7) + 8 * ((lane >> 3) & 1)) * KROWB
                                       + (lane >> 4) * 16);               // non-trans (K)
    const uint32_t v_lane = (uint32_t)((lane & 15) * KROWB + ((lane >> 4) << 4)); // trans (V)

    // ---- stage Q via smem (32 KB, overlays tile buffers), build A-fragments.
    //      Q pre-scaled by log2e -> scores in log2 units. ----
    {
        float* qstage = (float*)sm;
        const float4* qp = (const float4*)(qg + base + (long long)q0 * DIM);
        float4* st = (float4*)qstage;
        #pragma unroll
        for (int e = tid; e < MQ_CTA * 16; e += NTHREADS) st[e] = qp[e];
        __syncthreads();
    }
    uint32_t qfh[4][4], qfl[4][4];
    {
        const float* qstage = (const float*)sm;
        const int rr = 16 * warp + g;
        #pragma unroll
        for (int s = 0; s < 4; s++) {
            const int c = 16 * s + tg * 2;
            float2 x0 = *(const float2*)(qstage + rr * DIM + c);
            float2 x1 = *(const float2*)(qstage + (rr + 8) * DIM + c);
            float2 x2 = *(const float2*)(qstage + rr * DIM + c + 8);
            float2 x3 = *(const float2*)(qstage + (rr + 8) * DIM + c + 8);
            split2(x0.x * LOG2E, x0.y * LOG2E, qfh[s][0], qfl[s][0]);
            split2(x1.x * LOG2E, x1.y * LOG2E, qfh[s][1], qfl[s][1]);
            split2(x2.x * LOG2E, x2.y * LOG2E, qfh[s][2], qfl[s][2]);
            split2(x3.x * LOG2E, x3.y * LOG2E, qfh[s][3], qfl[s][3]);
        }
    }
    __syncthreads();

    // ---- tile loader: 64 keys -> K hi/lo (bf16) + V (fp16), key-major ----
    auto load_tile = [&](int t, int buf) {
        char* tb = sm + buf * TILE_BYTES;
        const int kt_a = q0 - WINDOW + t * TKEYS;
        #pragma unroll
        for (int e = tid; e < TKEYS * 16; e += NTHREADS) {   // 4 iterations
            const int jj = e >> 4, c4 = e & 15;
            const int ja = kt_a + jj;
            float4 kk = make_float4(0.f, 0.f, 0.f, 0.f), vv = kk;
            if (ja >= 0) {
                const long long off = base + (long long)ja * DIM;
                kk = ((const float4*)(kg + off))[c4];
                vv = ((const float4*)(vg + off))[c4];
            }
            const uint32_t ro = (uint32_t)(jj * KROWB + c4 * 8);
            uint2 h, l;
            split2(kk.x, kk.y, h.x, l.x);
            split2(kk.z, kk.w, h.y, l.y);
            *(uint2*)(tb + T_KHI + ro) = h;
            *(uint2*)(tb + T_KLO + ro) = l;
            uint2 vp;
            vp.x = packh2(vv.x, vv.y);
            vp.y = packh2(vv.z, vv.w);
            *(uint2*)(tb + T_V + ro) = vp;
        }
    };

    float oacc[8][4];
    #pragma unroll
    for (int n = 0; n < 8; n++)
        #pragma unroll
        for (int c = 0; c < 4; c++) oacc[n][c] = 0.f;
    float lsum0 = 0.f, lsum1 = 0.f;
    float m0 = -1e30f, m1 = -1e30f;   // running max (log2 units)

    const int rw = q0 + 16 * warp;
    const int r0 = rw + g;
    const int r1 = r0 + 8;

    load_tile(0, 0);
    __syncthreads();

    for (int t = 0; t < NTILES; t++) {
        if (t + 1 < NTILES) load_tile(t + 1, (t + 1) & 1);

        const uint32_t tbu = smem_b + (uint32_t)((t & 1) * TILE_BYTES);
        const int kt_a = q0 - WINDOW + t * TKEYS;

        #pragma unroll
        for (int sblk = 0; sblk < 2; sblk++) {
            const int ktr = 32 * sblk;
            const int kta = kt_a + ktr;
            if (kta + 31 < rw - (WINDOW - 1) || kta > rw + 15 || kta + 31 < 0) continue;

            const bool fast = (kta >= 0) && (kta >= rw - (WINDOW - 16)) && (kta + 31 <= rw);

            // ---- S (log2 units) = (Q*log2e) K^T, bf16 3-product ----
            float sacc[4][4];
            #pragma unroll
            for (int n = 0; n < 4; n++)
                #pragma unroll
                for (int c = 0; c < 4; c++) sacc[n][c] = 0.f;

            const uint32_t kb = tbu + T_KHI + (uint32_t)(ktr * KROWB) + k_lane;
            #pragma unroll
            for (int ks = 0; ks < 4; ks++) {
                uint32_t bh[4][2], bl[4][2];
                #pragma unroll
                for (int p = 0; p < 2; p++) {
                    const uint32_t ah = kb + (uint32_t)(p * 16 * KROWB + ks * 32);
                    LDMX4(bh[2*p][0], bh[2*p+1][0], bh[2*p][1], bh[2*p+1][1], ah);
                    LDMX4(bl[2*p][0], bl[2*p+1][0], bl[2*p][1], bl[2*p+1][1],
                          ah + (T_KLO - T_KHI));
                }
                #pragma unroll
                for (int nt = 0; nt < 4; nt++) {
                    mma_bf16(sacc[nt], qfh[ks], bh[nt]);
                    mma_bf16(sacc[nt], qfh[ks], bl[nt]);
                    mma_bf16(sacc[nt], qfl[ks], bh[nt]);
                }
            }

            // ---- mask (slow path), online max, conditional rescale ----
            if (!fast) {
                #pragma unroll
                for (int nt = 0; nt < 4; nt++) {
                    const int j0 = kta + 8 * nt + tg * 2;
                    const int j1 = j0 + 1;
                    if (!((unsigned)(r0 - j0) < 256u && j0 >= 0)) sacc[nt][0] = -1e30f;
                    if (!((unsigned)(r0 - j1) < 256u && j1 >= 0)) sacc[nt][1] = -1e30f;
                    if (!((unsigned)(r1 - j0) < 256u && j0 >= 0)) sacc[nt][2] = -1e30f;
                    if (!((unsigned)(r1 - j1) < 256u && j1 >= 0)) sacc[nt][3] = -1e30f;
                }
            }
            float mx0 = fmaxf(fmaxf(fmaxf(sacc[0][0], sacc[0][1]), fmaxf(sacc[1][0], sacc[1][1])),
                              fmaxf(fmaxf(sacc[2][0], sacc[2][1]), fmaxf(sacc[3][0], sacc[3][1])));
            float mx1 = fmaxf(fmaxf(fmaxf(sacc[0][2], sacc[0][3]), fmaxf(sacc[1][2], sacc[1][3])),
                              fmaxf(fmaxf(sacc[2][2], sacc[2][3]), fmaxf(sacc[3][2], sacc[3][3])));
            mx0 = fmaxf(mx0, __shfl_xor_sync(0xffffffffu, mx0, 1));
            mx0 = fmaxf(mx0, __shfl_xor_sync(0xffffffffu, mx0, 2));
            mx1 = fmaxf(mx1, __shfl_xor_sync(0xffffffffu, mx1, 1));
            mx1 = fmaxf(mx1, __shfl_xor_sync(0xffffffffu, mx1, 2));
            const float m0n = fmaxf(m0, mx0);
            const float m1n = fmaxf(m1, mx1);
            const bool nochange = (m0n == m0) && (m1n == m1);
            if (!__all_sync(0xffffffffu, nochange)) {
                const float a0 = ex2f(m0 - m0n);
                const float a1 = ex2f(m1 - m1n);
                lsum0 *= a0; lsum1 *= a1;
                #pragma unroll
                for (int nt = 0; nt < 8; nt++) {
                    oacc[nt][0] *= a0; oacc[nt][1] *= a0;
                    oacc[nt][2] *= a1; oacc[nt][3] *= a1;
                }
                m0 = m0n; m1 = m1n;
            }

            // ---- p = 2^(s - m), pack P (fp16) ----
            uint32_t pf[2][4];
            if (fast) {
                #pragma unroll
                for (int nt = 0; nt < 4; nt++) {
                    const float p0 = ex2f(sacc[nt][0] - m0);
                    const float p1 = ex2f(sacc[nt][1] - m0);
                    const float p2 = ex2f(sacc[nt][2] - m1);
                    const float p3 = ex2f(sacc[nt][3] - m1);
                    lsum0 += p0 + p1;
                    lsum1 += p2 + p3;
                    const int kk = nt >> 1;
                    const int hh = (nt & 1) ? 2 : 0;
                    pf[kk][hh + 0] = packh2(p0, p1);
                    pf[kk][hh + 1] = packh2(p2, p3);
                }
            } else {
                #pragma unroll
                for (int nt = 0; nt < 4; nt++) {
                    const float p0 = (sacc[nt][0] > -1e29f) ? ex2f(sacc[nt][0] - m0) : 0.f;
                    const float p1 = (sacc[nt][1] > -1e29f) ? ex2f(sacc[nt][1] - m0) : 0.f;
                    const float p2 = (sacc[nt][2] > -1e29f) ? ex2f(sacc[nt][2] - m1) : 0.f;
                    const float p3 = (sacc[nt][3] > -1e29f) ? ex2f(sacc[nt][3] - m1) : 0.f;
                    lsum0 += p0 + p1;
                    lsum1 += p2 + p3;
                    const int kk = nt >> 1;
                    const int hh = (nt & 1) ? 2 : 0;
                    pf[kk][hh + 0] = packh2(p0, p1);
                    pf[kk][hh + 1] = packh2(p2, p3);
                }
            }

            // ---- O += P V (fp16), V-frags via ldmatrix.trans ----
            #pragma unroll
            for (int kk = 0; kk < 2; kk++) {
                const uint32_t vb = tbu + T_V + (uint32_t)((ktr + 16 * kk) * KROWB) + v_lane;
                #pragma unroll
                for (int p = 0; p < 4; p++) {
                    uint32_t vt[4];
                    LDMX4T(vt[0], vt[1], vt[2], vt[3], vb + (uint32_t)(p * 32));
                    mma_fp16(oacc[2*p],     pf[kk], vt);
                    mma_fp16(oacc[2*p + 1], pf[kk], vt + 2);
                }
            }
        }
        __syncthreads();
    }

    // ---- epilogue: quad-reduce row sums, normalize, store ----
    lsum0 += __shfl_xor_sync(0xffffffffu, lsum0, 1);
    lsum0 += __shfl_xor_sync(0xffffffffu, lsum0, 2);
    lsum1 += __shfl_xor_sync(0xffffffffu, lsum1, 1);
    lsum1 += __shfl_xor_sync(0xffffffffu, lsum1, 2);
    const float inv0 = 1.0f / lsum0;
    const float inv1 = 1.0f / lsum1;

    float* o0 = og + base + (long long)r0 * DIM;
    float* o1 = og + base + (long long)r1 * DIM;
    #pragma unroll
    for (int nt = 0; nt < 8; nt++) {
        const int d = 8 * nt + tg * 2;
        *(float2*)(o0 + d) = make_float2(oacc[nt][0] * inv0, oacc[nt][1] * inv0);
        *(float2*)(o1 + d) = make_float2(oacc[nt][2] * inv1, oacc[nt][3] * inv1);
    }
}

extern "C" void kernel_launch(void* const* d_in, const int* in_sizes, int n_in,
                              void* d_out, int out_size)
{
    const float* q = (const float*)d_in[0];
    const float* k = (const float*)d_in[1];
    const float* v = (const float*)d_in[2];
    float* out = (float*)d_out;

    static bool configured = false;
    if (!configured) {
        cudaFuncSetAttribute(swa_mma_kernel,
                             cudaFuncAttributeMaxDynamicSharedMemorySize, SMEM_TOTAL);
        configured = true;
    }

    const int BH = in_sizes[0] / (S_LEN * DIM);
    dim3 grid(S_LEN / MQ_CTA, BH);
    swa_mma_kernel<<<grid, NTHREADS, SMEM_TOTAL>>>(q, k, v, out);
}